// round 13
// baseline (speedup 1.0000x reference)
#include <cuda_runtime.h>
#include <cuda_bf16.h>
#include <math.h>

#define BB 2
#define SS 2048
#define DD 1024
#define HH 16
#define DHH 64
#define RS (HH*SS)

// ---------------- scratch ----------------
__device__ __nv_bfloat16 g_qh_h[BB*HH*SS*DHH];
__device__ __nv_bfloat16 g_qh_l[BB*HH*SS*DHH];
__device__ __nv_bfloat16 g_kh_h[BB*HH*SS*DHH];
__device__ __nv_bfloat16 g_kh_l[BB*HH*SS*DHH];
__device__ __nv_bfloat16 g_vT_h[BB*DHH*SS];   // [b, e, t]
__device__ __nv_bfloat16 g_vT_l[BB*DHH*SS];
__device__ float g_oh[BB*HH*SS*DHH];
__device__ float g_mean[BB*SS*DHH];
__device__ float g_pm[(size_t)BB*HH*SS*32];   // per-tile-warp partial max (scaled)
__device__ float g_pl[(size_t)BB*HH*SS*32];   // per-tile-warp partial sumexp
__device__ float g_sm[BB*HH*SS];              // final row max (scaled)
__device__ float g_sil[BB*HH*SS];             // final 1/l

// ---------------- helpers ----------------
__device__ __forceinline__ unsigned smem_u32(const void* p) {
    unsigned a;
    asm("{ .reg .u64 t; cvta.to.shared.u64 t, %1; cvt.u32.u64 %0, t; }" : "=r"(a) : "l"(p));
    return a;
}

__device__ __forceinline__ void sts64(unsigned addr, unsigned long long v) {
    asm volatile("st.shared.b64 [%0], %1;" :: "r"(addr), "l"(v) : "memory");
}

__device__ __forceinline__ void ldsm4(unsigned addr, unsigned& r0, unsigned& r1,
                                      unsigned& r2, unsigned& r3) {
    asm volatile("ldmatrix.sync.aligned.m8n8.x4.shared.b16 {%0,%1,%2,%3}, [%4];"
        : "=r"(r0), "=r"(r1), "=r"(r2), "=r"(r3) : "r"(addr));
}

__device__ __forceinline__ void mma16816(float* c, const unsigned* a, const unsigned* b) {
    asm volatile("mma.sync.aligned.m16n8k16.row.col.f32.bf16.bf16.f32 "
        "{%0,%1,%2,%3}, {%4,%5,%6,%7}, {%8,%9}, {%0,%1,%2,%3};"
        : "+f"(c[0]), "+f"(c[1]), "+f"(c[2]), "+f"(c[3])
        : "r"(a[0]), "r"(a[1]), "r"(a[2]), "r"(a[3]), "r"(b[0]), "r"(b[1]));
}

__device__ __forceinline__ void split2(float a, float b, unsigned& hi, unsigned& lo) {
    __nv_bfloat162 h = __float22bfloat162_rn(make_float2(a, b));
    float2 hf = __bfloat1622float2(h);
    __nv_bfloat162 l = __float22bfloat162_rn(make_float2(a - hf.x, b - hf.y));
    hi = *(unsigned*)&h; lo = *(unsigned*)&l;
}

__device__ __forceinline__ void cp16(unsigned dst, const void* src) {
    asm volatile("cp.async.cg.shared.global [%0], [%1], 16;" :: "r"(dst), "l"(src));
}
#define CP_COMMIT() asm volatile("cp.async.commit_group;")
#define CP_WAIT0()  asm volatile("cp.async.wait_group 0;")

__device__ __forceinline__ void load_bf16_pair_cp(const __nv_bfloat16* __restrict__ srcH,
                                                  const __nv_bfloat16* __restrict__ srcL,
                                                  int rows, unsigned sh, unsigned sl,
                                                  int tid, int nthr) {
    int nch = rows * 8;
    for (int c = tid; c < nch; c += nthr) {
        int row = c >> 3, cg = c & 7;
        unsigned off = (unsigned)(row * 144 + cg * 16);
        cp16(sh + off, srcH + (size_t)row * 64 + cg * 8);
        cp16(sl + off, srcL + (size_t)row * 64 + cg * 8);
    }
}

#define STG 55296   // stage stride (AH 0, AL 18432, BH 36864, BL 46080)

// ---------------- kernel 1: projections (HMMA, double-buffered) ----------------
__global__ __launch_bounds__(256) void proj_mma(
    const float* __restrict__ q, const float* __restrict__ k, const float* __restrict__ v,
    const float* __restrict__ Wq, const float* __restrict__ bq,
    const float* __restrict__ Wk, const float* __restrict__ bk,
    const float* __restrict__ Wv, const float* __restrict__ bv)
{
    extern __shared__ char sm_[];
    unsigned sb = smem_u32(sm_);

    int tid = threadIdx.x, w = tid >> 5, lane = tid & 31;
    int mt = blockIdx.x, b = blockIdx.y, task = blockIdx.z;
    int s0 = mt * 128;

    const float *X, *W, *bias;
    __nv_bfloat16 *dstH = 0, *dstL = 0;
    int isV = 0;
    if (task < HH) {
        X = q + (size_t)b*SS*DD; W = Wq + (size_t)task*DHH*DD; bias = bq + task*DHH;
        dstH = g_qh_h + (size_t)(b*HH + task)*SS*DHH;
        dstL = g_qh_l + (size_t)(b*HH + task)*SS*DHH;
    } else if (task < 2*HH) {
        int h = task - HH;
        X = k + (size_t)b*SS*DD; W = Wk + (size_t)h*DHH*DD; bias = bk + h*DHH;
        dstH = g_kh_h + (size_t)(b*HH + h)*SS*DHH;
        dstL = g_kh_l + (size_t)(b*HH + h)*SS*DHH;
    } else {
        X = v + (size_t)b*SS*DD; W = Wv; bias = bv; isV = 1;
    }
    const float* Xb = X + (size_t)s0 * DD;

    float cf[8][4];
    #pragma unroll
    for (int nf = 0; nf < 8; nf++)
        #pragma unroll
        for (int i = 0; i < 4; i++) cf[nf][i] = 0.f;

    int lrow = lane & 15;
    unsigned lcol16 = (unsigned)(lane >> 4) * 16;

    float4 xr[8], wr[4];

    // prologue: chunk 0
    #pragma unroll
    for (int i = 0; i < 8; i++) {
        int idx = tid + i*256; int row = idx >> 4, cg = idx & 15;
        xr[i] = *(const float4*)&Xb[(size_t)row * DD + cg*4];
    }
    #pragma unroll
    for (int i = 0; i < 4; i++) {
        int idx = tid + i*256; int row = idx >> 4, cg = idx & 15;
        wr[i] = *(const float4*)&W[(size_t)row * DD + cg*4];
    }
    {
        unsigned st = sb;
        #pragma unroll
        for (int i = 0; i < 8; i++) {
            int idx = tid + i*256; int row = idx >> 4, cg = idx & 15;
            unsigned h0,l0,h1,l1;
            split2(xr[i].x, xr[i].y, h0, l0); split2(xr[i].z, xr[i].w, h1, l1);
            unsigned off = (unsigned)(row*144 + cg*8);
            sts64(st + off, ((unsigned long long)h1<<32)|h0);
            sts64(st + 18432 + off, ((unsigned long long)l1<<32)|l0);
        }
        #pragma unroll
        for (int i = 0; i < 4; i++) {
            int idx = tid + i*256; int row = idx >> 4, cg = idx & 15;
            unsigned h0,l0,h1,l1;
            split2(wr[i].x, wr[i].y, h0, l0); split2(wr[i].z, wr[i].w, h1, l1);
            unsigned off = (unsigned)(row*144 + cg*8);
            sts64(st + 36864 + off, ((unsigned long long)h1<<32)|h0);
            sts64(st + 46080 + off, ((unsigned long long)l1<<32)|l0);
        }
    }
    __syncthreads();

    for (int c = 0; c < 16; c++) {
        unsigned cur = sb + (unsigned)(c & 1) * STG;
        unsigned nxt = sb + (unsigned)((c + 1) & 1) * STG;
        bool more = (c < 15);
        if (more) {
            int k0 = (c + 1) * 64;
            #pragma unroll
            for (int i = 0; i < 8; i++) {
                int idx = tid + i*256; int row = idx >> 4, cg = idx & 15;
                xr[i] = *(const float4*)&Xb[(size_t)row * DD + k0 + cg*4];
            }
            #pragma unroll
            for (int i = 0; i < 4; i++) {
                int idx = tid + i*256; int row = idx >> 4, cg = idx & 15;
                wr[i] = *(const float4*)&W[(size_t)row * DD + k0 + cg*4];
            }
        }

        unsigned aBaseH = cur + (unsigned)(16*w + lrow) * 144 + lcol16;
        unsigned aBaseL = cur + 18432 + (unsigned)(16*w + lrow) * 144 + lcol16;
        #pragma unroll
        for (int ks = 0; ks < 4; ks++) {
            unsigned kb = (unsigned)ks * 32;
            unsigned aH[4], aL[4];
            ldsm4(aBaseH + kb, aH[0], aH[1], aH[2], aH[3]);
            ldsm4(aBaseL + kb, aL[0], aL[1], aL[2], aL[3]);
            unsigned bh[8][2], bl[8][2];
            #pragma unroll
            for (int nt2 = 0; nt2 < 4; nt2++) {
                unsigned r0, r1, r2, r3;
                unsigned boff = (unsigned)(nt2*16 + lrow) * 144 + lcol16 + kb;
                ldsm4(cur + 36864 + boff, r0, r1, r2, r3);
                bh[2*nt2][0] = r0; bh[2*nt2][1] = r2;
                bh[2*nt2+1][0] = r1; bh[2*nt2+1][1] = r3;
                ldsm4(cur + 46080 + boff, r0, r1, r2, r3);
                bl[2*nt2][0] = r0; bl[2*nt2][1] = r2;
                bl[2*nt2+1][0] = r1; bl[2*nt2+1][1] = r3;
            }
            #pragma unroll
            for (int nf = 0; nf < 8; nf++) {
                mma16816(cf[nf], aH, bh[nf]);
                mma16816(cf[nf], aH, bl[nf]);
                mma16816(cf[nf], aL, bh[nf]);
            }
        }

        if (more) {
            #pragma unroll
            for (int i = 0; i < 8; i++) {
                int idx = tid + i*256; int row = idx >> 4, cg = idx & 15;
                unsigned h0,l0,h1,l1;
                split2(xr[i].x, xr[i].y, h0, l0); split2(xr[i].z, xr[i].w, h1, l1);
                unsigned off = (unsigned)(row*144 + cg*8);
                sts64(nxt + off, ((unsigned long long)h1<<32)|h0);
                sts64(nxt + 18432 + off, ((unsigned long long)l1<<32)|l0);
            }
            #pragma unroll
            for (int i = 0; i < 4; i++) {
                int idx = tid + i*256; int row = idx >> 4, cg = idx & 15;
                unsigned h0,l0,h1,l1;
                split2(wr[i].x, wr[i].y, h0, l0); split2(wr[i].z, wr[i].w, h1, l1);
                unsigned off = (unsigned)(row*144 + cg*8);
                sts64(nxt + 36864 + off, ((unsigned long long)h1<<32)|h0);
                sts64(nxt + 46080 + off, ((unsigned long long)l1<<32)|l0);
            }
        }
        __syncthreads();
    }

    // epilogue
    int row0 = s0 + 16*w + (lane >> 2);
    int colb = (lane & 3) * 2;
    if (!isV) {
        #pragma unroll
        for (int nf = 0; nf < 8; nf++) {
            int col = nf * 8 + colb;
            float b0 = __ldg(&bias[col]), b1 = __ldg(&bias[col + 1]);
            unsigned h, l;
            split2(cf[nf][0] + b0, cf[nf][1] + b1, h, l);
            *(unsigned*)&dstH[(size_t)row0 * DHH + col] = h;
            *(unsigned*)&dstL[(size_t)row0 * DHH + col] = l;
            split2(cf[nf][2] + b0, cf[nf][3] + b1, h, l);
            *(unsigned*)&dstH[(size_t)(row0 + 8) * DHH + col] = h;
            *(unsigned*)&dstL[(size_t)(row0 + 8) * DHH + col] = l;
        }
    } else {
        #pragma unroll
        for (int nf = 0; nf < 8; nf++) {
            int col = nf * 8 + colb;
            float b0 = __ldg(&bias[col]), b1 = __ldg(&bias[col + 1]);
            float vv[4] = {cf[nf][0] + b0, cf[nf][1] + b1, cf[nf][2] + b0, cf[nf][3] + b1};
            int rr[4] = {row0, row0, row0 + 8, row0 + 8};
            int cc[4] = {col, col + 1, col, col + 1};
            #pragma unroll
            for (int i = 0; i < 4; i++) {
                __nv_bfloat16 hb = __float2bfloat16(vv[i]);
                __nv_bfloat16 lb = __float2bfloat16(vv[i] - __bfloat162float(hb));
                g_vT_h[((size_t)b * DHH + cc[i]) * SS + rr[i]] = hb;
                g_vT_l[((size_t)b * DHH + cc[i]) * SS + rr[i]] = lb;
            }
        }
    }
}

// ---------------- kernel 2: QK^T raw scores + per-warp row stats; upper tiles zeros ----------------
__global__ __launch_bounds__(256) void score_mma(float* __restrict__ attn)
{
    int x = blockIdx.x;
    int mt = x >> 4, nt = x & 15;
    int m0 = mt * 128, n0 = nt * 128;
    int h = blockIdx.y, b = blockIdx.z;
    int tid = threadIdx.x, w = tid >> 5, lane = tid & 31;

    float* dstBase = attn + (((size_t)b * SS + m0) * HH + h) * SS + n0;

    if (nt > mt) {   // strictly-upper tile: zeros only
        float4 z = make_float4(0.f, 0.f, 0.f, 0.f);
        #pragma unroll
        for (int i = 0; i < 16; i++) {
            int fid = (tid + i * 256) * 4;
            int row = fid >> 7, col = fid & 127;
            *(float4*)(dstBase + (size_t)row * RS + col) = z;
        }
        return;
    }

    extern __shared__ char sm_[];
    unsigned sb = smem_u32(sm_);
    const unsigned QH = sb, QL = sb + 18432, KH = sb + 36864, KL = sb + 55296;

    size_t bh = (size_t)(b * HH + h);
    load_bf16_pair_cp(g_qh_h + (bh*SS + m0)*DHH, g_qh_l + (bh*SS + m0)*DHH, 128, QH, QL, tid, 256);
    load_bf16_pair_cp(g_kh_h + (bh*SS + n0)*DHH, g_kh_l + (bh*SS + n0)*DHH, 128, KH, KL, tid, 256);
    CP_COMMIT();
    CP_WAIT0();
    __syncthreads();

    int mw = w >> 1, nw = w & 1;
    int lrow = lane & 15;
    unsigned lcol16 = (unsigned)(lane >> 4) * 16;
    int grp = lane >> 2, tig = lane & 3;

    float cf[2][8][4];
    #pragma unroll
    for (int mf = 0; mf < 2; mf++)
        #pragma unroll
        for (int nf = 0; nf < 8; nf++)
            #pragma unroll
            for (int i = 0; i < 4; i++) cf[mf][nf][i] = 0.f;

    #pragma unroll
    for (int ks = 0; ks < 4; ks++) {
        unsigned kb = (unsigned)ks * 32;
        unsigned aH[2][4], aL[2][4];
        #pragma unroll
        for (int mf = 0; mf < 2; mf++) {
            unsigned aoff = (unsigned)(mw*32 + mf*16 + lrow) * 144 + lcol16 + kb;
            ldsm4(QH + aoff, aH[mf][0], aH[mf][1], aH[mf][2], aH[mf][3]);
            ldsm4(QL + aoff, aL[mf][0], aL[mf][1], aL[mf][2], aL[mf][3]);
        }
        unsigned bh2[8][2], bl2[8][2];
        #pragma unroll
        for (int nt2 = 0; nt2 < 4; nt2++) {
            unsigned boff = (unsigned)(nw*64 + nt2*16 + lrow) * 144 + lcol16 + kb;
            unsigned r0, r1, r2, r3;
            ldsm4(KH + boff, r0, r1, r2, r3);
            bh2[2*nt2][0] = r0; bh2[2*nt2][1] = r2;
            bh2[2*nt2+1][0] = r1; bh2[2*nt2+1][1] = r3;
            ldsm4(KL + boff, r0, r1, r2, r3);
            bl2[2*nt2][0] = r0; bl2[2*nt2][1] = r2;
            bl2[2*nt2+1][0] = r1; bl2[2*nt2+1][1] = r3;
        }
        #pragma unroll
        for (int mf = 0; mf < 2; mf++)
            #pragma unroll
            for (int nf = 0; nf < 8; nf++) {
                mma16816(cf[mf][nf], aH[mf], bh2[nf]);
                mma16816(cf[mf][nf], aH[mf], bl2[nf]);
                mma16816(cf[mf][nf], aL[mf], bh2[nf]);
            }
    }

    // ---- per-warp row stats (scaled, causal-masked) ----
    {
        bool diag = (nt == mt);
        int pt = nt * 2 + nw;
        #pragma unroll
        for (int mf = 0; mf < 2; mf++) {
            int rA = mw*32 + mf*16 + grp;        // local rows
            int rB = rA + 8;
            float mxA = -INFINITY, mxB = -INFINITY;
            #pragma unroll
            for (int nf = 0; nf < 8; nf++) {
                #pragma unroll
                for (int i = 0; i < 4; i++) {
                    int col = nw*64 + nf*8 + tig*2 + (i & 1);
                    int r = (i < 2) ? rA : rB;
                    bool vld = !diag || (n0 + col <= m0 + r);
                    float v = cf[mf][nf][i] * 0.125f;
                    if (vld) { if (i < 2) mxA = fmaxf(mxA, v); else mxB = fmaxf(mxB, v); }
                }
            }
            mxA = fmaxf(mxA, __shfl_xor_sync(0xffffffffu, mxA, 1));
            mxA = fmaxf(mxA, __shfl_xor_sync(0xffffffffu, mxA, 2));
            mxB = fmaxf(mxB, __shfl_xor_sync(0xffffffffu, mxB, 1));
            mxB = fmaxf(mxB, __shfl_xor_sync(0xffffffffu, mxB, 2));
            float lA = 0.f, lB = 0.f;
            #pragma unroll
            for (int nf = 0; nf < 8; nf++) {
                #pragma unroll
                for (int i = 0; i < 4; i++) {
                    int col = nw*64 + nf*8 + tig*2 + (i & 1);
                    int r = (i < 2) ? rA : rB;
                    bool vld = !diag || (n0 + col <= m0 + r);
                    if (vld) {
                        float v = cf[mf][nf][i] * 0.125f;
                        if (i < 2) lA += __expf(v - mxA); else lB += __expf(v - mxB);
                    }
                }
            }
            lA += __shfl_xor_sync(0xffffffffu, lA, 1);
            lA += __shfl_xor_sync(0xffffffffu, lA, 2);
            lB += __shfl_xor_sync(0xffffffffu, lB, 1);
            lB += __shfl_xor_sync(0xffffffffu, lB, 2);
            if (tig == 0) {
                size_t baseA = (bh * SS + (size_t)(m0 + rA)) * 32 + pt;
                size_t baseB = (bh * SS + (size_t)(m0 + rB)) * 32 + pt;
                g_pm[baseA] = mxA; g_pl[baseA] = lA;
                g_pm[baseB] = mxB; g_pl[baseB] = lB;
            }
        }
    }

    // ---- stage + write raw scores ----
    __syncthreads();
    int rbase = mw * 32 + grp;
    int cbase = nw * 64 + tig * 2;
    #pragma unroll
    for (int mf = 0; mf < 2; mf++)
        #pragma unroll
        for (int nf = 0; nf < 8; nf++) {
            int r = rbase + mf * 16, c = cbase + nf * 8;
            *(float2*)(sm_ + ((size_t)r * 132 + c) * 4) = make_float2(cf[mf][nf][0], cf[mf][nf][1]);
            *(float2*)(sm_ + ((size_t)(r + 8) * 132 + c) * 4) = make_float2(cf[mf][nf][2], cf[mf][nf][3]);
        }
    __syncthreads();

    #pragma unroll
    for (int i = 0; i < 16; i++) {
        int fid = (tid + i * 256) * 4;
        int row = fid >> 7, col = fid & 127;
        float4 f = *(const float4*)(sm_ + ((size_t)row * 132 + col) * 4);
        *(float4*)(dstBase + (size_t)row * RS + col) = f;
    }
}

// ---------------- kernel 3: combine partial stats -> (m, 1/l) per row ----------------
__global__ __launch_bounds__(256) void combine_k()
{
    int ridx = blockIdx.x * 8 + (threadIdx.x >> 5);   // global row index in [0, BB*HH*SS)
    int lane = threadIdx.x & 31;
    int s = ridx & (SS - 1);
    int npt = ((s >> 7) + 1) * 2;
    size_t base = (size_t)ridx * 32;
    float m = (lane < npt) ? g_pm[base + lane] : -INFINITY;
    float l = (lane < npt) ? g_pl[base + lane] : 0.f;
    float mm = m;
    #pragma unroll
    for (int o = 16; o > 0; o >>= 1) mm = fmaxf(mm, __shfl_xor_sync(0xffffffffu, mm, o));
    float lc = l * __expf(m - mm);
    #pragma unroll
    for (int o = 16; o > 0; o >>= 1) lc += __shfl_xor_sync(0xffffffffu, lc, o);
    if (lane == 0) { g_sm[ridx] = mm; g_sil[ridx] = 1.f / lc; }
}

// ---------------- kernel 4: PV GEMM + in-register normalization + final attn write ----------------
__global__ __launch_bounds__(256) void pvnorm_mma(float* __restrict__ attn)
{
    int mt = (int)(gridDim.x - 1 - blockIdx.x);
    int h = blockIdx.y, b = blockIdx.z;
    int m0 = mt * 128;
    int tid = threadIdx.x, w = tid >> 5, lane = tid & 31;

    extern __shared__ char sm_[];
    unsigned sb = smem_u32(sm_);

    size_t bh = (size_t)(b * HH + h);
    float* P = attn + (((size_t)b * SS + m0) * HH + h) * SS;
    const __nv_bfloat16* VHs = g_vT_h + (size_t)b * DHH * SS;
    const __nv_bfloat16* VLs = g_vT_l + (size_t)b * DHH * SS;

    // per-thread row stats: rows (tid>>4) + 16*i
    float m_r[8], il_r[8];
    #pragma unroll
    for (int i = 0; i < 8; i++) {
        int grow = m0 + (tid >> 4) + 16*i;
        size_t sidx = bh * SS + grow;
        m_r[i] = g_sm[sidx]; il_r[i] = g_sil[sidx];
    }

    float cf[8][4];
    #pragma unroll
    for (int nf = 0; nf < 8; nf++)
        #pragma unroll
        for (int i = 0; i < 4; i++) cf[nf][i] = 0.f;

    int lrow = lane & 15;
    unsigned lcol16 = (unsigned)(lane >> 4) * 16;

    int nchunks = 2 * mt + 2;
    float4 pr[8];

    // normalize raw pr -> probs; write final attn in-place; split to smem stage ST
    #define XFORM_STORE(T0, ST) do {                                              \
        bool needmask = ((T0) + 63 > m0);                                         \
        _Pragma("unroll")                                                         \
        for (int i = 0; i < 8; i++) {                                             \
            int idx = tid + i*256; int row = idx >> 4, cg = idx & 15;             \
            float mm = m_r[i], il = il_r[i];                                      \
            float4 p;                                                             \
            p.x = __expf(pr[i].x*0.125f - mm) * il;                               \
            p.y = __expf(pr[i].y*0.125f - mm) * il;                               \
            p.z = __expf(pr[i].z*0.125f - mm) * il;                               \
            p.w = __expf(pr[i].w*0.125f - mm) * il;                               \
            if (needmask) {                                                       \
                int grow = m0 + row, colb = (T0) + cg*4;                          \
                if (colb + 0 > grow) p.x = 0.f;                                   \
                if (colb + 1 > grow) p.y = 0.f;                                   \
                if (colb + 2 > grow) p.z = 0.f;                                   \
                if (colb + 3 > grow) p.w = 0.f;                                   \
            }                                                                     \
            *(float4*)&P[(size_t)row * RS + (T0) + cg*4] = p;                     \
            unsigned h0,l0,h1,l1;                                                 \
            split2(p.x, p.y, h0, l0); split2(p.z, p.w, h1, l1);                   \
            unsigned off = (unsigned)(row*144 + cg*8);                            \
            sts64((ST) + off, ((unsigned long long)h1<<32)|h0);                   \
            sts64((ST) + 18432 + off, ((unsigned long long)l1<<32)|l0);           \
        }                                                                         \
    } while (0)

    // prologue: chunk 0
    {
        unsigned st = sb;
        #pragma unroll
        for (int i = 0; i < 2; i++) {
            int idx = tid + i*256; int row = idx >> 3, cg = idx & 7;
            cp16(st + 36864 + (unsigned)(row*144 + cg*16), &VHs[(size_t)row * SS + cg*8]);
            cp16(st + 46080 + (unsigned)(row*144 + cg*16), &VLs[(size_t)row * SS + cg*8]);
        }
        CP_COMMIT();
        #pragma unroll
        for (int i = 0; i < 8; i++) {
            int idx = tid + i*256; int row = idx >> 4, cg = idx & 15;
            pr[i] = *(const float4*)&P[(size_t)row * RS + cg*4];
        }
        XFORM_STORE(0, st);
        CP_WAIT0();
    }
    __syncthreads();

    for (int c = 0; c < nchunks; c++) {
        unsigned cur = sb + (unsigned)(c & 1) * STG;
        unsigned nxt = sb + (unsigned)((c + 1) & 1) * STG;
        bool more = (c + 1 < nchunks);
        int t1 = (c + 1) * 64;
        if (more) {
            #pragma unroll
            for (int i = 0; i < 2; i++) {
                int idx = tid + i*256; int row = idx >> 3, cg = idx & 7;
                cp16(nxt + 36864 + (unsigned)(row*144 + cg*16), &VHs[(size_t)row * SS + t1 + cg*8]);
                cp16(nxt + 46080 + (unsigned)(row*144 + cg*16), &VLs[(size_t)row * SS + t1 + cg*8]);
            }
            CP_COMMIT();
            #pragma unroll
            for (int i = 0; i < 8; i++) {
                int idx = tid + i*256; int row = idx >> 4, cg = idx & 15;
                pr[i] = *(const float4*)&P[(size_t)row * RS + t1 + cg*4];
            }
        }

        unsigned aBaseH = cur + (unsigned)(16*w + lrow) * 144 + lcol16;
        unsigned aBaseL = cur + 18432 + (unsigned)(16*w + lrow) * 144 + lcol16;
        #pragma unroll
        for (int ks = 0; ks < 4; ks++) {
            unsigned kb = (unsigned)ks * 32;
            unsigned aH[4], aL[4];
            ldsm4(aBaseH + kb, aH[0], aH[1], aH[2], aH[3]);
            ldsm4(aBaseL + kb, aL[0], aL[1], aL[2], aL[3]);
            unsigned bh2[8][2], bl2[8][2];
            #pragma unroll
            for (int nt2 = 0; nt2 < 4; nt2++) {
                unsigned boff = (unsigned)(nt2*16 + lrow) * 144 + lcol16 + kb;
                unsigned r0, r1, r2, r3;
                ldsm4(cur + 36864 + boff, r0, r1, r2, r3);
                bh2[2*nt2][0] = r0; bh2[2*nt2][1] = r2;
                bh2[2*nt2+1][0] = r1; bh2[2*nt2+1][1] = r3;
                ldsm4(cur + 46080 + boff, r0, r1, r2, r3);
                bl2[2*nt2][0] = r0; bl2[2*nt2][1] = r2;
                bl2[2*nt2+1][0] = r1; bl2[2*nt2+1][1] = r3;
            }
            #pragma unroll
            for (int nf = 0; nf < 8; nf++) {
                mma16816(cf[nf], aH, bh2[nf]);
                mma16816(cf[nf], aH, bl2[nf]);
                mma16816(cf[nf], aL, bh2[nf]);
            }
        }

        if (more) {
            XFORM_STORE(t1, nxt);
            CP_WAIT0();
        }
        __syncthreads();
    }
    #undef XFORM_STORE

    int row0 = m0 + 16*w + (lane >> 2);
    int colb = (lane & 3) * 2;
    float* dst = g_oh + (bh * SS) * DHH;
    #pragma unroll
    for (int nf = 0; nf < 8; nf++) {
        int col = nf * 8 + colb;
        *(float2*)&dst[(size_t)row0 * DHH + col] = make_float2(cf[nf][0], cf[nf][1]);
        *(float2*)&dst[(size_t)(row0 + 8) * DHH + col] = make_float2(cf[nf][2], cf[nf][3]);
    }
}

// ---------------- kernel 5: mean over heads ----------------
__global__ __launch_bounds__(256) void mean_kernel()
{
    int idx = blockIdx.x * 256 + threadIdx.x;
    int e = idx & 63;
    int s = (idx >> 6) & (SS - 1);
    int b = idx >> 17;
    float sum = 0.f;
    #pragma unroll
    for (int h = 0; h < HH; h++)
        sum += g_oh[((size_t)(b*HH + h)*SS + s)*DHH + e];
    g_mean[idx] = sum * (1.f / 16.f);
}

// ---------------- kernel 6: output projection ----------------
__global__ __launch_bounds__(256) void outproj_kernel(const float* __restrict__ Wo,
                                                      float* __restrict__ out)
{
    __shared__ float ms[64][68];
    __shared__ float wsm[64][68];
    int s0 = blockIdx.x * 64, d0 = blockIdx.y * 64, b = blockIdx.z;
    int tid = threadIdx.x;
    int ty = tid >> 4, tx = tid & 15;
    int lr = tid >> 2;
    int le = (tid & 3) * 16;

    #pragma unroll
    for (int i = 0; i < 16; i += 4) {
        float4 f = *(const float4*)&g_mean[((size_t)b*SS + s0+lr)*DHH + le + i];
        ms[le+i+0][lr] = f.x; ms[le+i+1][lr] = f.y;
        ms[le+i+2][lr] = f.z; ms[le+i+3][lr] = f.w;
        float4 g = *(const float4*)&Wo[(size_t)(d0+lr)*DHH + le + i];
        wsm[le+i+0][lr] = g.x; wsm[le+i+1][lr] = g.y;
        wsm[le+i+2][lr] = g.z; wsm[le+i+3][lr] = g.w;
    }
    __syncthreads();

    float acc[4][4];
    #pragma unroll
    for (int i = 0; i < 4; i++)
        #pragma unroll
        for (int j = 0; j < 4; j++) acc[i][j] = 0.f;

    #pragma unroll 16
    for (int e = 0; e < 64; e++) {
        float4 mf = *(const float4*)&ms[e][ty*4];
        float4 wf = *(const float4*)&wsm[e][tx*4];
        float mr[4] = {mf.x, mf.y, mf.z, mf.w};
        float wr[4] = {wf.x, wf.y, wf.z, wf.w};
        #pragma unroll
        for (int i = 0; i < 4; i++)
            #pragma unroll
            for (int j = 0; j < 4; j++)
                acc[i][j] += mr[i] * wr[j];
    }

    #pragma unroll
    for (int i = 0; i < 4; i++) {
        float4 o;
        o.x = acc[i][0]; o.y = acc[i][1]; o.z = acc[i][2]; o.w = acc[i][3];
        *(float4*)&out[(size_t)b*SS*DD + (size_t)(s0 + ty*4 + i)*DD + d0 + tx*4] = o;
    }
}

// ---------------- launch ----------------
extern "C" void kernel_launch(void* const* d_in, const int* in_sizes, int n_in,
                              void* d_out, int out_size)
{
    (void)in_sizes; (void)n_in; (void)out_size;
    const float* q  = (const float*)d_in[0];
    const float* k  = (const float*)d_in[1];
    const float* v  = (const float*)d_in[2];
    const float* Wv = (const float*)d_in[4];
    const float* bv = (const float*)d_in[5];
    const float* Wq = (const float*)d_in[6];
    const float* bq = (const float*)d_in[7];
    const float* Wk = (const float*)d_in[8];
    const float* bk = (const float*)d_in[9];
    const float* Wo = (const float*)d_in[10];

    float* out  = (float*)d_out;
    float* attn = out + (size_t)BB*SS*DD;

    const int PROJ_SMEM  = 2 * STG;   // 110592
    const int SCORE_SMEM = 73728;
    const int PV_SMEM    = 2 * STG;   // 110592

    cudaFuncSetAttribute(proj_mma,   cudaFuncAttributeMaxDynamicSharedMemorySize, PROJ_SMEM);
    cudaFuncSetAttribute(score_mma,  cudaFuncAttributeMaxDynamicSharedMemorySize, SCORE_SMEM);
    cudaFuncSetAttribute(pvnorm_mma, cudaFuncAttributeMaxDynamicSharedMemorySize, PV_SMEM);

    proj_mma<<<dim3(SS/128, BB, 2*HH + 1), 256, PROJ_SMEM>>>(q, k, v, Wq, bq, Wk, bk, Wv, bv);
    score_mma<<<dim3(256, HH, BB), 256, SCORE_SMEM>>>(attn);
    combine_k<<<BB*HH*SS/8, 256>>>();
    pvnorm_mma<<<dim3(SS/128, HH, BB), 256, PV_SMEM>>>(attn);
    mean_kernel<<<BB*SS*DHH/256, 256>>>();
    outproj_kernel<<<dim3(SS/64, DD/64, BB), 256>>>(Wo, out);
}

// round 14
// speedup vs baseline: 1.0826x; 1.0826x over previous
#include <cuda_runtime.h>
#include <cuda_bf16.h>
#include <math.h>

#define BB 2
#define SS 2048
#define DD 1024
#define HH 16
#define DHH 64
#define RS (HH*SS)

// ---------------- scratch ----------------
__device__ __nv_bfloat16 g_qh_h[BB*HH*SS*DHH];
__device__ __nv_bfloat16 g_qh_l[BB*HH*SS*DHH];
__device__ __nv_bfloat16 g_kh_h[BB*HH*SS*DHH];
__device__ __nv_bfloat16 g_kh_l[BB*HH*SS*DHH];
__device__ __nv_bfloat16 g_vT_h[BB*DHH*SS];   // [b, e, t]
__device__ __nv_bfloat16 g_vT_l[BB*DHH*SS];
__device__ float g_oh[BB*HH*SS*DHH];
__device__ float g_mean[BB*SS*DHH];
__device__ float g_sm[BB*HH*SS];              // row max (scaled)
__device__ float g_sil[BB*HH*SS];             // row 1/l

// ---------------- helpers ----------------
__device__ __forceinline__ unsigned smem_u32(const void* p) {
    unsigned a;
    asm("{ .reg .u64 t; cvta.to.shared.u64 t, %1; cvt.u32.u64 %0, t; }" : "=r"(a) : "l"(p));
    return a;
}

__device__ __forceinline__ void sts64(unsigned addr, unsigned long long v) {
    asm volatile("st.shared.b64 [%0], %1;" :: "r"(addr), "l"(v) : "memory");
}

__device__ __forceinline__ void ldsm4(unsigned addr, unsigned& r0, unsigned& r1,
                                      unsigned& r2, unsigned& r3) {
    asm volatile("ldmatrix.sync.aligned.m8n8.x4.shared.b16 {%0,%1,%2,%3}, [%4];"
        : "=r"(r0), "=r"(r1), "=r"(r2), "=r"(r3) : "r"(addr));
}

__device__ __forceinline__ void mma16816(float* c, const unsigned* a, const unsigned* b) {
    asm volatile("mma.sync.aligned.m16n8k16.row.col.f32.bf16.bf16.f32 "
        "{%0,%1,%2,%3}, {%4,%5,%6,%7}, {%8,%9}, {%0,%1,%2,%3};"
        : "+f"(c[0]), "+f"(c[1]), "+f"(c[2]), "+f"(c[3])
        : "r"(a[0]), "r"(a[1]), "r"(a[2]), "r"(a[3]), "r"(b[0]), "r"(b[1]));
}

__device__ __forceinline__ void split2(float a, float b, unsigned& hi, unsigned& lo) {
    __nv_bfloat162 h = __float22bfloat162_rn(make_float2(a, b));
    float2 hf = __bfloat1622float2(h);
    __nv_bfloat162 l = __float22bfloat162_rn(make_float2(a - hf.x, b - hf.y));
    hi = *(unsigned*)&h; lo = *(unsigned*)&l;
}

__device__ __forceinline__ void cp16(unsigned dst, const void* src) {
    asm volatile("cp.async.cg.shared.global [%0], [%1], 16;" :: "r"(dst), "l"(src));
}
#define CP_COMMIT() asm volatile("cp.async.commit_group;")
#define CP_WAIT0()  asm volatile("cp.async.wait_group 0;")

__device__ __forceinline__ void load_bf16_pair_cp(const __nv_bfloat16* __restrict__ srcH,
                                                  const __nv_bfloat16* __restrict__ srcL,
                                                  int rows, unsigned sh, unsigned sl,
                                                  int tid, int nthr) {
    int nch = rows * 8;
    for (int c = tid; c < nch; c += nthr) {
        int row = c >> 3, cg = c & 7;
        unsigned off = (unsigned)(row * 144 + cg * 16);
        cp16(sh + off, srcH + (size_t)row * 64 + cg * 8);
        cp16(sl + off, srcL + (size_t)row * 64 + cg * 8);
    }
}

#define STG 55296   // stage stride (AH 0, AL 18432, BH 36864, BL 46080)

// ---------------- kernel 1: projections (HMMA, double-buffered) ----------------
__global__ __launch_bounds__(256) void proj_mma(
    const float* __restrict__ q, const float* __restrict__ k, const float* __restrict__ v,
    const float* __restrict__ Wq, const float* __restrict__ bq,
    const float* __restrict__ Wk, const float* __restrict__ bk,
    const float* __restrict__ Wv, const float* __restrict__ bv)
{
    extern __shared__ char sm_[];
    unsigned sb = smem_u32(sm_);

    int tid = threadIdx.x, w = tid >> 5, lane = tid & 31;
    int mt = blockIdx.x, b = blockIdx.y, task = blockIdx.z;
    int s0 = mt * 128;

    const float *X, *W, *bias;
    __nv_bfloat16 *dstH = 0, *dstL = 0;
    int isV = 0;
    if (task < HH) {
        X = q + (size_t)b*SS*DD; W = Wq + (size_t)task*DHH*DD; bias = bq + task*DHH;
        dstH = g_qh_h + (size_t)(b*HH + task)*SS*DHH;
        dstL = g_qh_l + (size_t)(b*HH + task)*SS*DHH;
    } else if (task < 2*HH) {
        int h = task - HH;
        X = k + (size_t)b*SS*DD; W = Wk + (size_t)h*DHH*DD; bias = bk + h*DHH;
        dstH = g_kh_h + (size_t)(b*HH + h)*SS*DHH;
        dstL = g_kh_l + (size_t)(b*HH + h)*SS*DHH;
    } else {
        X = v + (size_t)b*SS*DD; W = Wv; bias = bv; isV = 1;
    }
    const float* Xb = X + (size_t)s0 * DD;

    float cf[8][4];
    #pragma unroll
    for (int nf = 0; nf < 8; nf++)
        #pragma unroll
        for (int i = 0; i < 4; i++) cf[nf][i] = 0.f;

    int lrow = lane & 15;
    unsigned lcol16 = (unsigned)(lane >> 4) * 16;

    float4 xr[8], wr[4];

    // prologue: chunk 0
    #pragma unroll
    for (int i = 0; i < 8; i++) {
        int idx = tid + i*256; int row = idx >> 4, cg = idx & 15;
        xr[i] = *(const float4*)&Xb[(size_t)row * DD + cg*4];
    }
    #pragma unroll
    for (int i = 0; i < 4; i++) {
        int idx = tid + i*256; int row = idx >> 4, cg = idx & 15;
        wr[i] = *(const float4*)&W[(size_t)row * DD + cg*4];
    }
    {
        unsigned st = sb;
        #pragma unroll
        for (int i = 0; i < 8; i++) {
            int idx = tid + i*256; int row = idx >> 4, cg = idx & 15;
            unsigned h0,l0,h1,l1;
            split2(xr[i].x, xr[i].y, h0, l0); split2(xr[i].z, xr[i].w, h1, l1);
            unsigned off = (unsigned)(row*144 + cg*8);
            sts64(st + off, ((unsigned long long)h1<<32)|h0);
            sts64(st + 18432 + off, ((unsigned long long)l1<<32)|l0);
        }
        #pragma unroll
        for (int i = 0; i < 4; i++) {
            int idx = tid + i*256; int row = idx >> 4, cg = idx & 15;
            unsigned h0,l0,h1,l1;
            split2(wr[i].x, wr[i].y, h0, l0); split2(wr[i].z, wr[i].w, h1, l1);
            unsigned off = (unsigned)(row*144 + cg*8);
            sts64(st + 36864 + off, ((unsigned long long)h1<<32)|h0);
            sts64(st + 46080 + off, ((unsigned long long)l1<<32)|l0);
        }
    }
    __syncthreads();

    for (int c = 0; c < 16; c++) {
        unsigned cur = sb + (unsigned)(c & 1) * STG;
        unsigned nxt = sb + (unsigned)((c + 1) & 1) * STG;
        bool more = (c < 15);
        if (more) {
            int k0 = (c + 1) * 64;
            #pragma unroll
            for (int i = 0; i < 8; i++) {
                int idx = tid + i*256; int row = idx >> 4, cg = idx & 15;
                xr[i] = *(const float4*)&Xb[(size_t)row * DD + k0 + cg*4];
            }
            #pragma unroll
            for (int i = 0; i < 4; i++) {
                int idx = tid + i*256; int row = idx >> 4, cg = idx & 15;
                wr[i] = *(const float4*)&W[(size_t)row * DD + k0 + cg*4];
            }
        }

        unsigned aBaseH = cur + (unsigned)(16*w + lrow) * 144 + lcol16;
        unsigned aBaseL = cur + 18432 + (unsigned)(16*w + lrow) * 144 + lcol16;
        #pragma unroll
        for (int ks = 0; ks < 4; ks++) {
            unsigned kb = (unsigned)ks * 32;
            unsigned aH[4], aL[4];
            ldsm4(aBaseH + kb, aH[0], aH[1], aH[2], aH[3]);
            ldsm4(aBaseL + kb, aL[0], aL[1], aL[2], aL[3]);
            unsigned bh[8][2], bl[8][2];
            #pragma unroll
            for (int nt2 = 0; nt2 < 4; nt2++) {
                unsigned r0, r1, r2, r3;
                unsigned boff = (unsigned)(nt2*16 + lrow) * 144 + lcol16 + kb;
                ldsm4(cur + 36864 + boff, r0, r1, r2, r3);
                bh[2*nt2][0] = r0; bh[2*nt2][1] = r2;
                bh[2*nt2+1][0] = r1; bh[2*nt2+1][1] = r3;
                ldsm4(cur + 46080 + boff, r0, r1, r2, r3);
                bl[2*nt2][0] = r0; bl[2*nt2][1] = r2;
                bl[2*nt2+1][0] = r1; bl[2*nt2+1][1] = r3;
            }
            #pragma unroll
            for (int nf = 0; nf < 8; nf++) {
                mma16816(cf[nf], aH, bh[nf]);
                mma16816(cf[nf], aH, bl[nf]);
                mma16816(cf[nf], aL, bh[nf]);
            }
        }

        if (more) {
            #pragma unroll
            for (int i = 0; i < 8; i++) {
                int idx = tid + i*256; int row = idx >> 4, cg = idx & 15;
                unsigned h0,l0,h1,l1;
                split2(xr[i].x, xr[i].y, h0, l0); split2(xr[i].z, xr[i].w, h1, l1);
                unsigned off = (unsigned)(row*144 + cg*8);
                sts64(nxt + off, ((unsigned long long)h1<<32)|h0);
                sts64(nxt + 18432 + off, ((unsigned long long)l1<<32)|l0);
            }
            #pragma unroll
            for (int i = 0; i < 4; i++) {
                int idx = tid + i*256; int row = idx >> 4, cg = idx & 15;
                unsigned h0,l0,h1,l1;
                split2(wr[i].x, wr[i].y, h0, l0); split2(wr[i].z, wr[i].w, h1, l1);
                unsigned off = (unsigned)(row*144 + cg*8);
                sts64(nxt + 36864 + off, ((unsigned long long)h1<<32)|h0);
                sts64(nxt + 46080 + off, ((unsigned long long)l1<<32)|l0);
            }
        }
        __syncthreads();
    }

    // epilogue
    int row0 = s0 + 16*w + (lane >> 2);
    int colb = (lane & 3) * 2;
    if (!isV) {
        #pragma unroll
        for (int nf = 0; nf < 8; nf++) {
            int col = nf * 8 + colb;
            float b0 = __ldg(&bias[col]), b1 = __ldg(&bias[col + 1]);
            unsigned h, l;
            split2(cf[nf][0] + b0, cf[nf][1] + b1, h, l);
            *(unsigned*)&dstH[(size_t)row0 * DHH + col] = h;
            *(unsigned*)&dstL[(size_t)row0 * DHH + col] = l;
            split2(cf[nf][2] + b0, cf[nf][3] + b1, h, l);
            *(unsigned*)&dstH[(size_t)(row0 + 8) * DHH + col] = h;
            *(unsigned*)&dstL[(size_t)(row0 + 8) * DHH + col] = l;
        }
    } else {
        #pragma unroll
        for (int nf = 0; nf < 8; nf++) {
            int col = nf * 8 + colb;
            float b0 = __ldg(&bias[col]), b1 = __ldg(&bias[col + 1]);
            float vv[4] = {cf[nf][0] + b0, cf[nf][1] + b1, cf[nf][2] + b0, cf[nf][3] + b1};
            int rr[4] = {row0, row0, row0 + 8, row0 + 8};
            int cc[4] = {col, col + 1, col, col + 1};
            #pragma unroll
            for (int i = 0; i < 4; i++) {
                __nv_bfloat16 hb = __float2bfloat16(vv[i]);
                __nv_bfloat16 lb = __float2bfloat16(vv[i] - __bfloat162float(hb));
                g_vT_h[((size_t)b * DHH + cc[i]) * SS + rr[i]] = hb;
                g_vT_l[((size_t)b * DHH + cc[i]) * SS + rr[i]] = lb;
            }
        }
    }
}

// ---------------- kernel 2: QK^T raw scores; upper tiles stream zeros ----------------
__global__ __launch_bounds__(256) void score_mma(float* __restrict__ attn)
{
    int x = blockIdx.x;
    int mt = x >> 4, nt = x & 15;
    int m0 = mt * 128, n0 = nt * 128;
    int h = blockIdx.y, b = blockIdx.z;
    int tid = threadIdx.x, w = tid >> 5, lane = tid & 31;

    float* dstBase = attn + (((size_t)b * SS + m0) * HH + h) * SS + n0;

    if (nt > mt) {   // strictly-upper tile: zeros only
        float4 z = make_float4(0.f, 0.f, 0.f, 0.f);
        #pragma unroll
        for (int i = 0; i < 16; i++) {
            int fid = (tid + i * 256) * 4;
            int row = fid >> 7, col = fid & 127;
            *(float4*)(dstBase + (size_t)row * RS + col) = z;
        }
        return;
    }

    extern __shared__ char sm_[];
    unsigned sb = smem_u32(sm_);
    const unsigned QH = sb, QL = sb + 18432, KH = sb + 36864, KL = sb + 55296;

    size_t bh = (size_t)(b * HH + h);
    load_bf16_pair_cp(g_qh_h + (bh*SS + m0)*DHH, g_qh_l + (bh*SS + m0)*DHH, 128, QH, QL, tid, 256);
    load_bf16_pair_cp(g_kh_h + (bh*SS + n0)*DHH, g_kh_l + (bh*SS + n0)*DHH, 128, KH, KL, tid, 256);
    CP_COMMIT();
    CP_WAIT0();
    __syncthreads();

    int mw = w >> 1, nw = w & 1;
    int lrow = lane & 15;
    unsigned lcol16 = (unsigned)(lane >> 4) * 16;

    float cf[2][8][4];
    #pragma unroll
    for (int mf = 0; mf < 2; mf++)
        #pragma unroll
        for (int nf = 0; nf < 8; nf++)
            #pragma unroll
            for (int i = 0; i < 4; i++) cf[mf][nf][i] = 0.f;

    #pragma unroll
    for (int ks = 0; ks < 4; ks++) {
        unsigned kb = (unsigned)ks * 32;
        unsigned aH[2][4], aL[2][4];
        #pragma unroll
        for (int mf = 0; mf < 2; mf++) {
            unsigned aoff = (unsigned)(mw*32 + mf*16 + lrow) * 144 + lcol16 + kb;
            ldsm4(QH + aoff, aH[mf][0], aH[mf][1], aH[mf][2], aH[mf][3]);
            ldsm4(QL + aoff, aL[mf][0], aL[mf][1], aL[mf][2], aL[mf][3]);
        }
        unsigned bh2[8][2], bl2[8][2];
        #pragma unroll
        for (int nt2 = 0; nt2 < 4; nt2++) {
            unsigned boff = (unsigned)(nw*64 + nt2*16 + lrow) * 144 + lcol16 + kb;
            unsigned r0, r1, r2, r3;
            ldsm4(KH + boff, r0, r1, r2, r3);
            bh2[2*nt2][0] = r0; bh2[2*nt2][1] = r2;
            bh2[2*nt2+1][0] = r1; bh2[2*nt2+1][1] = r3;
            ldsm4(KL + boff, r0, r1, r2, r3);
            bl2[2*nt2][0] = r0; bl2[2*nt2][1] = r2;
            bl2[2*nt2+1][0] = r1; bl2[2*nt2+1][1] = r3;
        }
        #pragma unroll
        for (int mf = 0; mf < 2; mf++)
            #pragma unroll
            for (int nf = 0; nf < 8; nf++) {
                mma16816(cf[mf][nf], aH[mf], bh2[nf]);
                mma16816(cf[mf][nf], aH[mf], bl2[nf]);
                mma16816(cf[mf][nf], aL[mf], bh2[nf]);
            }
    }

    __syncthreads();
    int rbase = mw * 32 + (lane >> 2);
    int cbase = nw * 64 + (lane & 3) * 2;
    #pragma unroll
    for (int mf = 0; mf < 2; mf++)
        #pragma unroll
        for (int nf = 0; nf < 8; nf++) {
            int r = rbase + mf * 16, c = cbase + nf * 8;
            *(float2*)(sm_ + ((size_t)r * 132 + c) * 4) = make_float2(cf[mf][nf][0], cf[mf][nf][1]);
            *(float2*)(sm_ + ((size_t)(r + 8) * 132 + c) * 4) = make_float2(cf[mf][nf][2], cf[mf][nf][3]);
        }
    __syncthreads();

    #pragma unroll
    for (int i = 0; i < 16; i++) {
        int fid = (tid + i * 256) * 4;
        int row = fid >> 7, col = fid & 127;
        float4 f = *(const float4*)(sm_ + ((size_t)row * 132 + col) * 4);
        *(float4*)(dstBase + (size_t)row * RS + col) = f;
    }
}

// ---------------- kernel 3: row stats only (read-only sweep) ----------------
__global__ __launch_bounds__(128) void stats_k(const float* __restrict__ attn)
{
    int row = blockIdx.x;                    // ((b*S + s)*H + h)
    int s = (row >> 4) & (SS - 1);
    const float* p = attn + (size_t)row * SS;
    int tid = threadIdx.x;
    __shared__ float red[4];

    float vals[16];
    float mx = -INFINITY;
    #pragma unroll
    for (int i = 0; i < 4; i++) {
        int ci = i * 128 + tid;
        int t0 = ci * 4;
        if (t0 + 3 <= s) {
            float4 f = ((const float4*)p)[ci];
            float v0 = f.x*0.125f, v1 = f.y*0.125f, v2 = f.z*0.125f, v3 = f.w*0.125f;
            vals[i*4+0]=v0; vals[i*4+1]=v1; vals[i*4+2]=v2; vals[i*4+3]=v3;
            mx = fmaxf(fmaxf(mx, fmaxf(v0, v1)), fmaxf(v2, v3));
        } else if (t0 <= s) {
            float4 f = ((const float4*)p)[ci];
            float v0 = f.x*0.125f, v1 = f.y*0.125f, v2 = f.z*0.125f, v3 = f.w*0.125f;
            vals[i*4+0]=v0; vals[i*4+1]=v1; vals[i*4+2]=v2; vals[i*4+3]=v3;
            mx = fmaxf(mx, v0);
            if (t0+1 <= s) mx = fmaxf(mx, v1);
            if (t0+2 <= s) mx = fmaxf(mx, v2);
        } else {
            vals[i*4+0]=0.f; vals[i*4+1]=0.f; vals[i*4+2]=0.f; vals[i*4+3]=0.f;
        }
    }
    #pragma unroll
    for (int o = 16; o > 0; o >>= 1) mx = fmaxf(mx, __shfl_xor_sync(0xffffffffu, mx, o));
    if ((tid & 31) == 0) red[tid >> 5] = mx;
    __syncthreads();
    mx = fmaxf(fmaxf(red[0], red[1]), fmaxf(red[2], red[3]));
    __syncthreads();

    float sum = 0.f;
    #pragma unroll
    for (int i = 0; i < 4; i++) {
        int t0 = (i * 128 + tid) * 4;
        if (t0 + 3 <= s) {
            #pragma unroll
            for (int j = 0; j < 4; j++) sum += __expf(vals[i*4+j] - mx);
        } else if (t0 <= s) {
            #pragma unroll
            for (int j = 0; j < 4; j++)
                if (t0 + j <= s) sum += __expf(vals[i*4+j] - mx);
        }
    }
    #pragma unroll
    for (int o = 16; o > 0; o >>= 1) sum += __shfl_xor_sync(0xffffffffu, sum, o);
    if ((tid & 31) == 0) red[tid >> 5] = sum;
    __syncthreads();
    if (tid == 0) {
        g_sm[row]  = mx;
        g_sil[row] = 1.f / (red[0] + red[1] + red[2] + red[3]);
    }
}

// ---------------- kernel 4: PV GEMM + in-register normalization + final attn write ----------------
__global__ __launch_bounds__(256) void pvnorm_mma(float* __restrict__ attn)
{
    int mt = (int)(gridDim.x - 1 - blockIdx.x);
    int h = blockIdx.y, b = blockIdx.z;
    int m0 = mt * 128;
    int tid = threadIdx.x, w = tid >> 5, lane = tid & 31;

    extern __shared__ char sm_[];
    unsigned sb = smem_u32(sm_);

    size_t bh = (size_t)(b * HH + h);
    float* P = attn + (((size_t)b * SS + m0) * HH + h) * SS;
    const __nv_bfloat16* VHs = g_vT_h + (size_t)b * DHH * SS;
    const __nv_bfloat16* VLs = g_vT_l + (size_t)b * DHH * SS;

    // per-thread row stats (row index = (tid>>4) + 16*i; stats indexed by attn row layout (b*S+s)*H + h)
    float m_r[8], il_r[8];
    #pragma unroll
    for (int i = 0; i < 8; i++) {
        int grow = m0 + (tid >> 4) + 16*i;
        size_t sidx = (((size_t)b * SS + grow) * HH + h);
        m_r[i] = g_sm[sidx]; il_r[i] = g_sil[sidx];
    }

    float cf[8][4];
    #pragma unroll
    for (int nf = 0; nf < 8; nf++)
        #pragma unroll
        for (int i = 0; i < 4; i++) cf[nf][i] = 0.f;

    int lrow = lane & 15;
    unsigned lcol16 = (unsigned)(lane >> 4) * 16;

    int nchunks = 2 * mt + 2;
    float4 pr[8];

    #define XFORM_STORE(T0, ST) do {                                              \
        bool needmask = ((T0) + 63 > m0);                                         \
        _Pragma("unroll")                                                         \
        for (int i = 0; i < 8; i++) {                                             \
            int idx = tid + i*256; int row = idx >> 4, cg = idx & 15;             \
            float mm = m_r[i], il = il_r[i];                                      \
            float4 p;                                                             \
            p.x = __expf(pr[i].x*0.125f - mm) * il;                               \
            p.y = __expf(pr[i].y*0.125f - mm) * il;                               \
            p.z = __expf(pr[i].z*0.125f - mm) * il;                               \
            p.w = __expf(pr[i].w*0.125f - mm) * il;                               \
            if (needmask) {                                                       \
                int grow = m0 + row, colb = (T0) + cg*4;                          \
                if (colb + 0 > grow) p.x = 0.f;                                   \
                if (colb + 1 > grow) p.y = 0.f;                                   \
                if (colb + 2 > grow) p.z = 0.f;                                   \
                if (colb + 3 > grow) p.w = 0.f;                                   \
            }                                                                     \
            *(float4*)&P[(size_t)row * RS + (T0) + cg*4] = p;                     \
            unsigned h0,l0,h1,l1;                                                 \
            split2(p.x, p.y, h0, l0); split2(p.z, p.w, h1, l1);                   \
            unsigned off = (unsigned)(row*144 + cg*8);                            \
            sts64((ST) + off, ((unsigned long long)h1<<32)|h0);                   \
            sts64((ST) + 18432 + off, ((unsigned long long)l1<<32)|l0);           \
        }                                                                         \
    } while (0)

    // prologue: chunk 0
    {
        unsigned st = sb;
        #pragma unroll
        for (int i = 0; i < 2; i++) {
            int idx = tid + i*256; int row = idx >> 3, cg = idx & 7;
            cp16(st + 36864 + (unsigned)(row*144 + cg*16), &VHs[(size_t)row * SS + cg*8]);
            cp16(st + 46080 + (unsigned)(row*144 + cg*16), &VLs[(size_t)row * SS + cg*8]);
        }
        CP_COMMIT();
        #pragma unroll
        for (int i = 0; i < 8; i++) {
            int idx = tid + i*256; int row = idx >> 4, cg = idx & 15;
            pr[i] = *(const float4*)&P[(size_t)row * RS + cg*4];
        }
        XFORM_STORE(0, st);
        CP_WAIT0();
    }
    __syncthreads();

    for (int c = 0; c < nchunks; c++) {
        unsigned cur = sb + (unsigned)(c & 1) * STG;
        unsigned nxt = sb + (unsigned)((c + 1) & 1) * STG;
        bool more = (c + 1 < nchunks);
        int t1 = (c + 1) * 64;
        if (more) {
            #pragma unroll
            for (int i = 0; i < 2; i++) {
                int idx = tid + i*256; int row = idx >> 3, cg = idx & 7;
                cp16(nxt + 36864 + (unsigned)(row*144 + cg*16), &VHs[(size_t)row * SS + t1 + cg*8]);
                cp16(nxt + 46080 + (unsigned)(row*144 + cg*16), &VLs[(size_t)row * SS + t1 + cg*8]);
            }
            CP_COMMIT();
            #pragma unroll
            for (int i = 0; i < 8; i++) {
                int idx = tid + i*256; int row = idx >> 4, cg = idx & 15;
                pr[i] = *(const float4*)&P[(size_t)row * RS + t1 + cg*4];
            }
        }

        unsigned aBaseH = cur + (unsigned)(16*w + lrow) * 144 + lcol16;
        unsigned aBaseL = cur + 18432 + (unsigned)(16*w + lrow) * 144 + lcol16;
        #pragma unroll
        for (int ks = 0; ks < 4; ks++) {
            unsigned kb = (unsigned)ks * 32;
            unsigned aH[4], aL[4];
            ldsm4(aBaseH + kb, aH[0], aH[1], aH[2], aH[3]);
            ldsm4(aBaseL + kb, aL[0], aL[1], aL[2], aL[3]);
            unsigned bh2[8][2], bl2[8][2];
            #pragma unroll
            for (int nt2 = 0; nt2 < 4; nt2++) {
                unsigned boff = (unsigned)(nt2*16 + lrow) * 144 + lcol16 + kb;
                unsigned r0, r1, r2, r3;
                ldsm4(cur + 36864 + boff, r0, r1, r2, r3);
                bh2[2*nt2][0] = r0; bh2[2*nt2][1] = r2;
                bh2[2*nt2+1][0] = r1; bh2[2*nt2+1][1] = r3;
                ldsm4(cur + 46080 + boff, r0, r1, r2, r3);
                bl2[2*nt2][0] = r0; bl2[2*nt2][1] = r2;
                bl2[2*nt2+1][0] = r1; bl2[2*nt2+1][1] = r3;
            }
            #pragma unroll
            for (int nf = 0; nf < 8; nf++) {
                mma16816(cf[nf], aH, bh2[nf]);
                mma16816(cf[nf], aH, bl2[nf]);
                mma16816(cf[nf], aL, bh2[nf]);
            }
        }

        if (more) {
            XFORM_STORE(t1, nxt);
            CP_WAIT0();
        }
        __syncthreads();
    }
    #undef XFORM_STORE

    int row0 = m0 + 16*w + (lane >> 2);
    int colb = (lane & 3) * 2;
    float* dst = g_oh + (bh * SS) * DHH;
    #pragma unroll
    for (int nf = 0; nf < 8; nf++) {
        int col = nf * 8 + colb;
        *(float2*)&dst[(size_t)row0 * DHH + col] = make_float2(cf[nf][0], cf[nf][1]);
        *(float2*)&dst[(size_t)(row0 + 8) * DHH + col] = make_float2(cf[nf][2], cf[nf][3]);
    }
}

// ---------------- kernel 5: mean over heads ----------------
__global__ __launch_bounds__(256) void mean_kernel()
{
    int idx = blockIdx.x * 256 + threadIdx.x;
    int e = idx & 63;
    int s = (idx >> 6) & (SS - 1);
    int b = idx >> 17;
    float sum = 0.f;
    #pragma unroll
    for (int h = 0; h < HH; h++)
        sum += g_oh[((size_t)(b*HH + h)*SS + s)*DHH + e];
    g_mean[idx] = sum * (1.f / 16.f);
}

// ---------------- kernel 6: output projection ----------------
__global__ __launch_bounds__(256) void outproj_kernel(const float* __restrict__ Wo,
                                                      float* __restrict__ out)
{
    __shared__ float ms[64][68];
    __shared__ float wsm[64][68];
    int s0 = blockIdx.x * 64, d0 = blockIdx.y * 64, b = blockIdx.z;
    int tid = threadIdx.x;
    int ty = tid >> 4, tx = tid & 15;
    int lr = tid >> 2;
    int le = (tid & 3) * 16;

    #pragma unroll
    for (int i = 0; i < 16; i += 4) {
        float4 f = *(const float4*)&g_mean[((size_t)b*SS + s0+lr)*DHH + le + i];
        ms[le+i+0][lr] = f.x; ms[le+i+1][lr] = f.y;
        ms[le+i+2][lr] = f.z; ms[le+i+3][lr] = f.w;
        float4 g = *(const float4*)&Wo[(size_t)(d0+lr)*DHH + le + i];
        wsm[le+i+0][lr] = g.x; wsm[le+i+1][lr] = g.y;
        wsm[le+i+2][lr] = g.z; wsm[le+i+3][lr] = g.w;
    }
    __syncthreads();

    float acc[4][4];
    #pragma unroll
    for (int i = 0; i < 4; i++)
        #pragma unroll
        for (int j = 0; j < 4; j++) acc[i][j] = 0.f;

    #pragma unroll 16
    for (int e = 0; e < 64; e++) {
        float4 mf = *(const float4*)&ms[e][ty*4];
        float4 wf = *(const float4*)&wsm[e][tx*4];
        float mr[4] = {mf.x, mf.y, mf.z, mf.w};
        float wr[4] = {wf.x, wf.y, wf.z, wf.w};
        #pragma unroll
        for (int i = 0; i < 4; i++)
            #pragma unroll
            for (int j = 0; j < 4; j++)
                acc[i][j] += mr[i] * wr[j];
    }

    #pragma unroll
    for (int i = 0; i < 4; i++) {
        float4 o;
        o.x = acc[i][0]; o.y = acc[i][1]; o.z = acc[i][2]; o.w = acc[i][3];
        *(float4*)&out[(size_t)b*SS*DD + (size_t)(s0 + ty*4 + i)*DD + d0 + tx*4] = o;
    }
}

// ---------------- launch ----------------
extern "C" void kernel_launch(void* const* d_in, const int* in_sizes, int n_in,
                              void* d_out, int out_size)
{
    (void)in_sizes; (void)n_in; (void)out_size;
    const float* q  = (const float*)d_in[0];
    const float* k  = (const float*)d_in[1];
    const float* v  = (const float*)d_in[2];
    const float* Wv = (const float*)d_in[4];
    const float* bv = (const float*)d_in[5];
    const float* Wq = (const float*)d_in[6];
    const float* bq = (const float*)d_in[7];
    const float* Wk = (const float*)d_in[8];
    const float* bk = (const float*)d_in[9];
    const float* Wo = (const float*)d_in[10];

    float* out  = (float*)d_out;
    float* attn = out + (size_t)BB*SS*DD;

    const int PROJ_SMEM  = 2 * STG;   // 110592
    const int SCORE_SMEM = 73728;
    const int PV_SMEM    = 2 * STG;   // 110592

    cudaFuncSetAttribute(proj_mma,   cudaFuncAttributeMaxDynamicSharedMemorySize, PROJ_SMEM);
    cudaFuncSetAttribute(score_mma,  cudaFuncAttributeMaxDynamicSharedMemorySize, SCORE_SMEM);
    cudaFuncSetAttribute(pvnorm_mma, cudaFuncAttributeMaxDynamicSharedMemorySize, PV_SMEM);

    proj_mma<<<dim3(SS/128, BB, 2*HH + 1), 256, PROJ_SMEM>>>(q, k, v, Wq, bq, Wk, bk, Wv, bv);
    score_mma<<<dim3(256, HH, BB), 256, SCORE_SMEM>>>(attn);
    stats_k<<<BB*SS*HH, 128>>>(attn);
    pvnorm_mma<<<dim3(SS/128, HH, BB), 256, PV_SMEM>>>(attn);
    mean_kernel<<<BB*SS*DHH/256, 256>>>();
    outproj_kernel<<<dim3(SS/64, DD/64, BB), 256>>>(Wo, out);
}

// round 15
// speedup vs baseline: 1.1779x; 1.0881x over previous
#include <cuda_runtime.h>
#include <cuda_bf16.h>
#include <math.h>

#define BB 2
#define SS 2048
#define DD 1024
#define HH 16
#define DHH 64
#define RS (HH*SS)

// ---------------- scratch ----------------
__device__ __nv_bfloat16 g_qh_h[BB*HH*SS*DHH];
__device__ __nv_bfloat16 g_qh_l[BB*HH*SS*DHH];
__device__ __nv_bfloat16 g_kh_h[BB*HH*SS*DHH];
__device__ __nv_bfloat16 g_kh_l[BB*HH*SS*DHH];
__device__ __nv_bfloat16 g_vT_h[BB*DHH*SS];   // [b, e, t]
__device__ __nv_bfloat16 g_vT_l[BB*DHH*SS];
__device__ float g_oh[BB*HH*SS*DHH];
__device__ float g_mean[BB*SS*DHH];
__device__ float g_pl[(size_t)BB*HH*SS*32];   // per-(tile,half) partial sumexp
__device__ float g_sil[BB*HH*SS];             // row 1/l

// ---------------- helpers ----------------
__device__ __forceinline__ unsigned smem_u32(const void* p) {
    unsigned a;
    asm("{ .reg .u64 t; cvta.to.shared.u64 t, %1; cvt.u32.u64 %0, t; }" : "=r"(a) : "l"(p));
    return a;
}

__device__ __forceinline__ void sts64(unsigned addr, unsigned long long v) {
    asm volatile("st.shared.b64 [%0], %1;" :: "r"(addr), "l"(v) : "memory");
}

__device__ __forceinline__ void ldsm4(unsigned addr, unsigned& r0, unsigned& r1,
                                      unsigned& r2, unsigned& r3) {
    asm volatile("ldmatrix.sync.aligned.m8n8.x4.shared.b16 {%0,%1,%2,%3}, [%4];"
        : "=r"(r0), "=r"(r1), "=r"(r2), "=r"(r3) : "r"(addr));
}

__device__ __forceinline__ void mma16816(float* c, const unsigned* a, const unsigned* b) {
    asm volatile("mma.sync.aligned.m16n8k16.row.col.f32.bf16.bf16.f32 "
        "{%0,%1,%2,%3}, {%4,%5,%6,%7}, {%8,%9}, {%0,%1,%2,%3};"
        : "+f"(c[0]), "+f"(c[1]), "+f"(c[2]), "+f"(c[3])
        : "r"(a[0]), "r"(a[1]), "r"(a[2]), "r"(a[3]), "r"(b[0]), "r"(b[1]));
}

__device__ __forceinline__ void split2(float a, float b, unsigned& hi, unsigned& lo) {
    __nv_bfloat162 h = __float22bfloat162_rn(make_float2(a, b));
    float2 hf = __bfloat1622float2(h);
    __nv_bfloat162 l = __float22bfloat162_rn(make_float2(a - hf.x, b - hf.y));
    hi = *(unsigned*)&h; lo = *(unsigned*)&l;
}

__device__ __forceinline__ void cp16(unsigned dst, const void* src) {
    asm volatile("cp.async.cg.shared.global [%0], [%1], 16;" :: "r"(dst), "l"(src));
}
#define CP_COMMIT() asm volatile("cp.async.commit_group;")
#define CP_WAIT0()  asm volatile("cp.async.wait_group 0;")

__device__ __forceinline__ void load_bf16_pair_cp(const __nv_bfloat16* __restrict__ srcH,
                                                  const __nv_bfloat16* __restrict__ srcL,
                                                  int rows, unsigned sh, unsigned sl,
                                                  int tid, int nthr) {
    int nch = rows * 8;
    for (int c = tid; c < nch; c += nthr) {
        int row = c >> 3, cg = c & 7;
        unsigned off = (unsigned)(row * 144 + cg * 16);
        cp16(sh + off, srcH + (size_t)row * 64 + cg * 8);
        cp16(sl + off, srcL + (size_t)row * 64 + cg * 8);
    }
}

#define STG 55296   // stage stride (AH 0, AL 18432, BH 36864, BL 46080)

// ---------------- kernel 1: projections (HMMA, double-buffered) ----------------
__global__ __launch_bounds__(256) void proj_mma(
    const float* __restrict__ q, const float* __restrict__ k, const float* __restrict__ v,
    const float* __restrict__ Wq, const float* __restrict__ bq,
    const float* __restrict__ Wk, const float* __restrict__ bk,
    const float* __restrict__ Wv, const float* __restrict__ bv)
{
    extern __shared__ char sm_[];
    unsigned sb = smem_u32(sm_);

    int tid = threadIdx.x, w = tid >> 5, lane = tid & 31;
    int mt = blockIdx.x, b = blockIdx.y, task = blockIdx.z;
    int s0 = mt * 128;

    const float *X, *W, *bias;
    __nv_bfloat16 *dstH = 0, *dstL = 0;
    int isV = 0;
    if (task < HH) {
        X = q + (size_t)b*SS*DD; W = Wq + (size_t)task*DHH*DD; bias = bq + task*DHH;
        dstH = g_qh_h + (size_t)(b*HH + task)*SS*DHH;
        dstL = g_qh_l + (size_t)(b*HH + task)*SS*DHH;
    } else if (task < 2*HH) {
        int h = task - HH;
        X = k + (size_t)b*SS*DD; W = Wk + (size_t)h*DHH*DD; bias = bk + h*DHH;
        dstH = g_kh_h + (size_t)(b*HH + h)*SS*DHH;
        dstL = g_kh_l + (size_t)(b*HH + h)*SS*DHH;
    } else {
        X = v + (size_t)b*SS*DD; W = Wv; bias = bv; isV = 1;
    }
    const float* Xb = X + (size_t)s0 * DD;

    float cf[8][4];
    #pragma unroll
    for (int nf = 0; nf < 8; nf++)
        #pragma unroll
        for (int i = 0; i < 4; i++) cf[nf][i] = 0.f;

    int lrow = lane & 15;
    unsigned lcol16 = (unsigned)(lane >> 4) * 16;

    float4 xr[8], wr[4];

    // prologue: chunk 0
    #pragma unroll
    for (int i = 0; i < 8; i++) {
        int idx = tid + i*256; int row = idx >> 4, cg = idx & 15;
        xr[i] = *(const float4*)&Xb[(size_t)row * DD + cg*4];
    }
    #pragma unroll
    for (int i = 0; i < 4; i++) {
        int idx = tid + i*256; int row = idx >> 4, cg = idx & 15;
        wr[i] = *(const float4*)&W[(size_t)row * DD + cg*4];
    }
    {
        unsigned st = sb;
        #pragma unroll
        for (int i = 0; i < 8; i++) {
            int idx = tid + i*256; int row = idx >> 4, cg = idx & 15;
            unsigned h0,l0,h1,l1;
            split2(xr[i].x, xr[i].y, h0, l0); split2(xr[i].z, xr[i].w, h1, l1);
            unsigned off = (unsigned)(row*144 + cg*8);
            sts64(st + off, ((unsigned long long)h1<<32)|h0);
            sts64(st + 18432 + off, ((unsigned long long)l1<<32)|l0);
        }
        #pragma unroll
        for (int i = 0; i < 4; i++) {
            int idx = tid + i*256; int row = idx >> 4, cg = idx & 15;
            unsigned h0,l0,h1,l1;
            split2(wr[i].x, wr[i].y, h0, l0); split2(wr[i].z, wr[i].w, h1, l1);
            unsigned off = (unsigned)(row*144 + cg*8);
            sts64(st + 36864 + off, ((unsigned long long)h1<<32)|h0);
            sts64(st + 46080 + off, ((unsigned long long)l1<<32)|l0);
        }
    }
    __syncthreads();

    for (int c = 0; c < 16; c++) {
        unsigned cur = sb + (unsigned)(c & 1) * STG;
        unsigned nxt = sb + (unsigned)((c + 1) & 1) * STG;
        bool more = (c < 15);
        if (more) {
            int k0 = (c + 1) * 64;
            #pragma unroll
            for (int i = 0; i < 8; i++) {
                int idx = tid + i*256; int row = idx >> 4, cg = idx & 15;
                xr[i] = *(const float4*)&Xb[(size_t)row * DD + k0 + cg*4];
            }
            #pragma unroll
            for (int i = 0; i < 4; i++) {
                int idx = tid + i*256; int row = idx >> 4, cg = idx & 15;
                wr[i] = *(const float4*)&W[(size_t)row * DD + k0 + cg*4];
            }
        }

        unsigned aBaseH = cur + (unsigned)(16*w + lrow) * 144 + lcol16;
        unsigned aBaseL = cur + 18432 + (unsigned)(16*w + lrow) * 144 + lcol16;
        #pragma unroll
        for (int ks = 0; ks < 4; ks++) {
            unsigned kb = (unsigned)ks * 32;
            unsigned aH[4], aL[4];
            ldsm4(aBaseH + kb, aH[0], aH[1], aH[2], aH[3]);
            ldsm4(aBaseL + kb, aL[0], aL[1], aL[2], aL[3]);
            unsigned bh[8][2], bl[8][2];
            #pragma unroll
            for (int nt2 = 0; nt2 < 4; nt2++) {
                unsigned r0, r1, r2, r3;
                unsigned boff = (unsigned)(nt2*16 + lrow) * 144 + lcol16 + kb;
                ldsm4(cur + 36864 + boff, r0, r1, r2, r3);
                bh[2*nt2][0] = r0; bh[2*nt2][1] = r2;
                bh[2*nt2+1][0] = r1; bh[2*nt2+1][1] = r3;
                ldsm4(cur + 46080 + boff, r0, r1, r2, r3);
                bl[2*nt2][0] = r0; bl[2*nt2][1] = r2;
                bl[2*nt2+1][0] = r1; bl[2*nt2+1][1] = r3;
            }
            #pragma unroll
            for (int nf = 0; nf < 8; nf++) {
                mma16816(cf[nf], aH, bh[nf]);
                mma16816(cf[nf], aH, bl[nf]);
                mma16816(cf[nf], aL, bh[nf]);
            }
        }

        if (more) {
            #pragma unroll
            for (int i = 0; i < 8; i++) {
                int idx = tid + i*256; int row = idx >> 4, cg = idx & 15;
                unsigned h0,l0,h1,l1;
                split2(xr[i].x, xr[i].y, h0, l0); split2(xr[i].z, xr[i].w, h1, l1);
                unsigned off = (unsigned)(row*144 + cg*8);
                sts64(nxt + off, ((unsigned long long)h1<<32)|h0);
                sts64(nxt + 18432 + off, ((unsigned long long)l1<<32)|l0);
            }
            #pragma unroll
            for (int i = 0; i < 4; i++) {
                int idx = tid + i*256; int row = idx >> 4, cg = idx & 15;
                unsigned h0,l0,h1,l1;
                split2(wr[i].x, wr[i].y, h0, l0); split2(wr[i].z, wr[i].w, h1, l1);
                unsigned off = (unsigned)(row*144 + cg*8);
                sts64(nxt + 36864 + off, ((unsigned long long)h1<<32)|h0);
                sts64(nxt + 46080 + off, ((unsigned long long)l1<<32)|l0);
            }
        }
        __syncthreads();
    }

    // epilogue
    int row0 = s0 + 16*w + (lane >> 2);
    int colb = (lane & 3) * 2;
    if (!isV) {
        #pragma unroll
        for (int nf = 0; nf < 8; nf++) {
            int col = nf * 8 + colb;
            float b0 = __ldg(&bias[col]), b1 = __ldg(&bias[col + 1]);
            unsigned h, l;
            split2(cf[nf][0] + b0, cf[nf][1] + b1, h, l);
            *(unsigned*)&dstH[(size_t)row0 * DHH + col] = h;
            *(unsigned*)&dstL[(size_t)row0 * DHH + col] = l;
            split2(cf[nf][2] + b0, cf[nf][3] + b1, h, l);
            *(unsigned*)&dstH[(size_t)(row0 + 8) * DHH + col] = h;
            *(unsigned*)&dstL[(size_t)(row0 + 8) * DHH + col] = l;
        }
    } else {
        #pragma unroll
        for (int nf = 0; nf < 8; nf++) {
            int col = nf * 8 + colb;
            float b0 = __ldg(&bias[col]), b1 = __ldg(&bias[col + 1]);
            float vv[4] = {cf[nf][0] + b0, cf[nf][1] + b1, cf[nf][2] + b0, cf[nf][3] + b1};
            int rr[4] = {row0, row0, row0 + 8, row0 + 8};
            int cc[4] = {col, col + 1, col, col + 1};
            #pragma unroll
            for (int i = 0; i < 4; i++) {
                __nv_bfloat16 hb = __float2bfloat16(vv[i]);
                __nv_bfloat16 lb = __float2bfloat16(vv[i] - __bfloat162float(hb));
                g_vT_h[((size_t)b * DHH + cc[i]) * SS + rr[i]] = hb;
                g_vT_l[((size_t)b * DHH + cc[i]) * SS + rr[i]] = lb;
            }
        }
    }
}

// ---------------- kernel 2: QK^T raw scores + per-warp partial sumexp; upper tiles zeros ----------------
__global__ __launch_bounds__(256) void score_mma(float* __restrict__ attn)
{
    int x = blockIdx.x;
    int mt = x >> 4, nt = x & 15;
    int m0 = mt * 128, n0 = nt * 128;
    int h = blockIdx.y, b = blockIdx.z;
    int tid = threadIdx.x, w = tid >> 5, lane = tid & 31;

    float* dstBase = attn + (((size_t)b * SS + m0) * HH + h) * SS + n0;

    if (nt > mt) {   // strictly-upper tile: zeros only
        float4 z = make_float4(0.f, 0.f, 0.f, 0.f);
        #pragma unroll
        for (int i = 0; i < 16; i++) {
            int fid = (tid + i * 256) * 4;
            int row = fid >> 7, col = fid & 127;
            *(float4*)(dstBase + (size_t)row * RS + col) = z;
        }
        return;
    }

    extern __shared__ char sm_[];
    unsigned sb = smem_u32(sm_);
    const unsigned QH = sb, QL = sb + 18432, KH = sb + 36864, KL = sb + 55296;

    size_t bh = (size_t)(b * HH + h);
    load_bf16_pair_cp(g_qh_h + (bh*SS + m0)*DHH, g_qh_l + (bh*SS + m0)*DHH, 128, QH, QL, tid, 256);
    load_bf16_pair_cp(g_kh_h + (bh*SS + n0)*DHH, g_kh_l + (bh*SS + n0)*DHH, 128, KH, KL, tid, 256);
    CP_COMMIT();
    CP_WAIT0();
    __syncthreads();

    int mw = w >> 1, nw = w & 1;
    int lrow = lane & 15;
    unsigned lcol16 = (unsigned)(lane >> 4) * 16;
    int grp = lane >> 2, tig = lane & 3;

    float cf[2][8][4];
    #pragma unroll
    for (int mf = 0; mf < 2; mf++)
        #pragma unroll
        for (int nf = 0; nf < 8; nf++)
            #pragma unroll
            for (int i = 0; i < 4; i++) cf[mf][nf][i] = 0.f;

    #pragma unroll
    for (int ks = 0; ks < 4; ks++) {
        unsigned kb = (unsigned)ks * 32;
        unsigned aH[2][4], aL[2][4];
        #pragma unroll
        for (int mf = 0; mf < 2; mf++) {
            unsigned aoff = (unsigned)(mw*32 + mf*16 + lrow) * 144 + lcol16 + kb;
            ldsm4(QH + aoff, aH[mf][0], aH[mf][1], aH[mf][2], aH[mf][3]);
            ldsm4(QL + aoff, aL[mf][0], aL[mf][1], aL[mf][2], aL[mf][3]);
        }
        unsigned bh2[8][2], bl2[8][2];
        #pragma unroll
        for (int nt2 = 0; nt2 < 4; nt2++) {
            unsigned boff = (unsigned)(nw*64 + nt2*16 + lrow) * 144 + lcol16 + kb;
            unsigned r0, r1, r2, r3;
            ldsm4(KH + boff, r0, r1, r2, r3);
            bh2[2*nt2][0] = r0; bh2[2*nt2][1] = r2;
            bh2[2*nt2+1][0] = r1; bh2[2*nt2+1][1] = r3;
            ldsm4(KL + boff, r0, r1, r2, r3);
            bl2[2*nt2][0] = r0; bl2[2*nt2][1] = r2;
            bl2[2*nt2+1][0] = r1; bl2[2*nt2+1][1] = r3;
        }
        #pragma unroll
        for (int mf = 0; mf < 2; mf++)
            #pragma unroll
            for (int nf = 0; nf < 8; nf++) {
                mma16816(cf[mf][nf], aH[mf], bh2[nf]);
                mma16816(cf[mf][nf], aH[mf], bl2[nf]);
                mma16816(cf[mf][nf], aL[mf], bh2[nf]);
            }
    }

    // ---- per-warp partial sumexp (no max shift; diag-masked) ----
    {
        bool diag = (nt == mt);
        int pt = nt * 2 + nw;
        #pragma unroll
        for (int mf = 0; mf < 2; mf++) {
            int rA = mw*32 + mf*16 + grp, rB = rA + 8;
            float lA = 0.f, lB = 0.f;
            #pragma unroll
            for (int nf = 0; nf < 8; nf++) {
                #pragma unroll
                for (int i = 0; i < 4; i++) {
                    float e = __expf(cf[mf][nf][i] * 0.125f);
                    if (diag) {
                        int col = nw*64 + nf*8 + tig*2 + (i & 1);
                        int r = (i < 2) ? rA : rB;
                        if (n0 + col > m0 + r) e = 0.f;
                    }
                    if (i < 2) lA += e; else lB += e;
                }
            }
            lA += __shfl_xor_sync(0xffffffffu, lA, 1);
            lA += __shfl_xor_sync(0xffffffffu, lA, 2);
            lB += __shfl_xor_sync(0xffffffffu, lB, 1);
            lB += __shfl_xor_sync(0xffffffffu, lB, 2);
            if (tig == 0) {
                g_pl[(bh * SS + (size_t)(m0 + rA)) * 32 + pt] = lA;
                g_pl[(bh * SS + (size_t)(m0 + rB)) * 32 + pt] = lB;
            }
        }
    }

    // ---- stage + write raw scores ----
    __syncthreads();
    int rbase = mw * 32 + grp;
    int cbase = nw * 64 + tig * 2;
    #pragma unroll
    for (int mf = 0; mf < 2; mf++)
        #pragma unroll
        for (int nf = 0; nf < 8; nf++) {
            int r = rbase + mf * 16, c = cbase + nf * 8;
            *(float2*)(sm_ + ((size_t)r * 132 + c) * 4) = make_float2(cf[mf][nf][0], cf[mf][nf][1]);
            *(float2*)(sm_ + ((size_t)(r + 8) * 132 + c) * 4) = make_float2(cf[mf][nf][2], cf[mf][nf][3]);
        }
    __syncthreads();

    #pragma unroll
    for (int i = 0; i < 16; i++) {
        int fid = (tid + i * 256) * 4;
        int row = fid >> 7, col = fid & 127;
        float4 f = *(const float4*)(sm_ + ((size_t)row * 132 + col) * 4);
        *(float4*)(dstBase + (size_t)row * RS + col) = f;
    }
}

// ---------------- kernel 3: combine partial sumexp -> 1/l per row ----------------
__global__ __launch_bounds__(256) void combine_k()
{
    int ridx = blockIdx.x * 8 + (threadIdx.x >> 5);   // (bh*SS + s)
    int lane = threadIdx.x & 31;
    int s = ridx & (SS - 1);
    int npt = ((s >> 7) + 1) * 2;
    size_t base = (size_t)ridx * 32;
    float l = (lane < npt) ? g_pl[base + lane] : 0.f;
    #pragma unroll
    for (int o = 16; o > 0; o >>= 1) l += __shfl_xor_sync(0xffffffffu, l, o);
    if (lane == 0) {
        // convert (bh, s) index to attn row layout (b*S + s)*H + h for pvnorm's convenience? keep bh*SS+s
        g_sil[ridx] = 1.f / l;
    }
}

// ---------------- kernel 4: PV GEMM + in-register normalization + final attn write ----------------
__global__ __launch_bounds__(256) void pvnorm_mma(float* __restrict__ attn)
{
    int mt = (int)(gridDim.x - 1 - blockIdx.x);
    int h = blockIdx.y, b = blockIdx.z;
    int m0 = mt * 128;
    int tid = threadIdx.x, w = tid >> 5, lane = tid & 31;

    extern __shared__ char sm_[];
    unsigned sb = smem_u32(sm_);

    size_t bh = (size_t)(b * HH + h);
    float* P = attn + (((size_t)b * SS + m0) * HH + h) * SS;
    const __nv_bfloat16* VHs = g_vT_h + (size_t)b * DHH * SS;
    const __nv_bfloat16* VLs = g_vT_l + (size_t)b * DHH * SS;

    float il_r[8];
    #pragma unroll
    for (int i = 0; i < 8; i++) {
        int grow = m0 + (tid >> 4) + 16*i;
        il_r[i] = g_sil[bh * SS + grow];
    }

    float cf[8][4];
    #pragma unroll
    for (int nf = 0; nf < 8; nf++)
        #pragma unroll
        for (int i = 0; i < 4; i++) cf[nf][i] = 0.f;

    int lrow = lane & 15;
    unsigned lcol16 = (unsigned)(lane >> 4) * 16;

    int nchunks = 2 * mt + 2;
    float4 pr[8];

    #define XFORM_STORE(T0, ST) do {                                              \
        bool needmask = ((T0) + 63 > m0);                                         \
        _Pragma("unroll")                                                         \
        for (int i = 0; i < 8; i++) {                                             \
            int idx = tid + i*256; int row = idx >> 4, cg = idx & 15;             \
            float il = il_r[i];                                                   \
            float4 p;                                                             \
            p.x = __expf(pr[i].x*0.125f) * il;                                    \
            p.y = __expf(pr[i].y*0.125f) * il;                                    \
            p.z = __expf(pr[i].z*0.125f) * il;                                    \
            p.w = __expf(pr[i].w*0.125f) * il;                                    \
            if (needmask) {                                                       \
                int grow = m0 + row, colb = (T0) + cg*4;                          \
                if (colb + 0 > grow) p.x = 0.f;                                   \
                if (colb + 1 > grow) p.y = 0.f;                                   \
                if (colb + 2 > grow) p.z = 0.f;                                   \
                if (colb + 3 > grow) p.w = 0.f;                                   \
            }                                                                     \
            *(float4*)&P[(size_t)row * RS + (T0) + cg*4] = p;                     \
            unsigned h0,l0,h1,l1;                                                 \
            split2(p.x, p.y, h0, l0); split2(p.z, p.w, h1, l1);                   \
            unsigned off = (unsigned)(row*144 + cg*8);                            \
            sts64((ST) + off, ((unsigned long long)h1<<32)|h0);                   \
            sts64((ST) + 18432 + off, ((unsigned long long)l1<<32)|l0);           \
        }                                                                         \
    } while (0)

    // prologue: chunk 0
    {
        unsigned st = sb;
        #pragma unroll
        for (int i = 0; i < 2; i++) {
            int idx = tid + i*256; int row = idx >> 3, cg = idx & 7;
            cp16(st + 36864 + (unsigned)(row*144 + cg*16), &VHs[(size_t)row * SS + cg*8]);
            cp16(st + 46080 + (unsigned)(row*144 + cg*16), &VLs[(size_t)row * SS + cg*8]);
        }
        CP_COMMIT();
        #pragma unroll
        for (int i = 0; i < 8; i++) {
            int idx = tid + i*256; int row = idx >> 4, cg = idx & 15;
            pr[i] = *(const float4*)&P[(size_t)row * RS + cg*4];
        }
        XFORM_STORE(0, st);
        CP_WAIT0();
    }
    __syncthreads();

    for (int c = 0; c < nchunks; c++) {
        unsigned cur = sb + (unsigned)(c & 1) * STG;
        unsigned nxt = sb + (unsigned)((c + 1) & 1) * STG;
        bool more = (c + 1 < nchunks);
        int t1 = (c + 1) * 64;
        if (more) {
            #pragma unroll
            for (int i = 0; i < 2; i++) {
                int idx = tid + i*256; int row = idx >> 3, cg = idx & 7;
                cp16(nxt + 36864 + (unsigned)(row*144 + cg*16), &VHs[(size_t)row * SS + t1 + cg*8]);
                cp16(nxt + 46080 + (unsigned)(row*144 + cg*16), &VLs[(size_t)row * SS + t1 + cg*8]);
            }
            CP_COMMIT();
            #pragma unroll
            for (int i = 0; i < 8; i++) {
                int idx = tid + i*256; int row = idx >> 4, cg = idx & 15;
                pr[i] = *(const float4*)&P[(size_t)row * RS + t1 + cg*4];
            }
        }

        unsigned aBaseH = cur + (unsigned)(16*w + lrow) * 144 + lcol16;
        unsigned aBaseL = cur + 18432 + (unsigned)(16*w + lrow) * 144 + lcol16;
        #pragma unroll
        for (int ks = 0; ks < 4; ks++) {
            unsigned kb = (unsigned)ks * 32;
            unsigned aH[4], aL[4];
            ldsm4(aBaseH + kb, aH[0], aH[1], aH[2], aH[3]);
            ldsm4(aBaseL + kb, aL[0], aL[1], aL[2], aL[3]);
            unsigned bh2[8][2], bl2[8][2];
            #pragma unroll
            for (int nt2 = 0; nt2 < 4; nt2++) {
                unsigned boff = (unsigned)(nt2*16 + lrow) * 144 + lcol16 + kb;
                unsigned r0, r1, r2, r3;
                ldsm4(cur + 36864 + boff, r0, r1, r2, r3);
                bh2[2*nt2][0] = r0; bh2[2*nt2][1] = r2;
                bh2[2*nt2+1][0] = r1; bh2[2*nt2+1][1] = r3;
                ldsm4(cur + 46080 + boff, r0, r1, r2, r3);
                bl2[2*nt2][0] = r0; bl2[2*nt2][1] = r2;
                bl2[2*nt2+1][0] = r1; bl2[2*nt2+1][1] = r3;
            }
            #pragma unroll
            for (int nf = 0; nf < 8; nf++) {
                mma16816(cf[nf], aH, bh2[nf]);
                mma16816(cf[nf], aH, bl2[nf]);
                mma16816(cf[nf], aL, bh2[nf]);
            }
        }

        if (more) {
            XFORM_STORE(t1, nxt);
            CP_WAIT0();
        }
        __syncthreads();
    }
    #undef XFORM_STORE

    int row0 = m0 + 16*w + (lane >> 2);
    int colb = (lane & 3) * 2;
    float* dst = g_oh + (bh * SS) * DHH;
    #pragma unroll
    for (int nf = 0; nf < 8; nf++) {
        int col = nf * 8 + colb;
        *(float2*)&dst[(size_t)row0 * DHH + col] = make_float2(cf[nf][0], cf[nf][1]);
        *(float2*)&dst[(size_t)(row0 + 8) * DHH + col] = make_float2(cf[nf][2], cf[nf][3]);
    }
}

// ---------------- kernel 5: mean over heads ----------------
__global__ __launch_bounds__(256) void mean_kernel()
{
    int idx = blockIdx.x * 256 + threadIdx.x;
    int e = idx & 63;
    int s = (idx >> 6) & (SS - 1);
    int b = idx >> 17;
    float sum = 0.f;
    #pragma unroll
    for (int h = 0; h < HH; h++)
        sum += g_oh[((size_t)(b*HH + h)*SS + s)*DHH + e];
    g_mean[idx] = sum * (1.f / 16.f);
}

// ---------------- kernel 6: output projection ----------------
__global__ __launch_bounds__(256) void outproj_kernel(const float* __restrict__ Wo,
                                                      float* __restrict__ out)
{
    __shared__ float ms[64][68];
    __shared__ float wsm[64][68];
    int s0 = blockIdx.x * 64, d0 = blockIdx.y * 64, b = blockIdx.z;
    int tid = threadIdx.x;
    int ty = tid >> 4, tx = tid & 15;
    int lr = tid >> 2;
    int le = (tid & 3) * 16;

    #pragma unroll
    for (int i = 0; i < 16; i += 4) {
        float4 f = *(const float4*)&g_mean[((size_t)b*SS + s0+lr)*DHH + le + i];
        ms[le+i+0][lr] = f.x; ms[le+i+1][lr] = f.y;
        ms[le+i+2][lr] = f.z; ms[le+i+3][lr] = f.w;
        float4 g = *(const float4*)&Wo[(size_t)(d0+lr)*DHH + le + i];
        wsm[le+i+0][lr] = g.x; wsm[le+i+1][lr] = g.y;
        wsm[le+i+2][lr] = g.z; wsm[le+i+3][lr] = g.w;
    }
    __syncthreads();

    float acc[4][4];
    #pragma unroll
    for (int i = 0; i < 4; i++)
        #pragma unroll
        for (int j = 0; j < 4; j++) acc[i][j] = 0.f;

    #pragma unroll 16
    for (int e = 0; e < 64; e++) {
        float4 mf = *(const float4*)&ms[e][ty*4];
        float4 wf = *(const float4*)&wsm[e][tx*4];
        float mr[4] = {mf.x, mf.y, mf.z, mf.w};
        float wr[4] = {wf.x, wf.y, wf.z, wf.w};
        #pragma unroll
        for (int i = 0; i < 4; i++)
            #pragma unroll
            for (int j = 0; j < 4; j++)
                acc[i][j] += mr[i] * wr[j];
    }

    #pragma unroll
    for (int i = 0; i < 4; i++) {
        float4 o;
        o.x = acc[i][0]; o.y = acc[i][1]; o.z = acc[i][2]; o.w = acc[i][3];
        *(float4*)&out[(size_t)b*SS*DD + (size_t)(s0 + ty*4 + i)*DD + d0 + tx*4] = o;
    }
}

// ---------------- launch ----------------
extern "C" void kernel_launch(void* const* d_in, const int* in_sizes, int n_in,
                              void* d_out, int out_size)
{
    (void)in_sizes; (void)n_in; (void)out_size;
    const float* q  = (const float*)d_in[0];
    const float* k  = (const float*)d_in[1];
    const float* v  = (const float*)d_in[2];
    const float* Wv = (const float*)d_in[4];
    const float* bv = (const float*)d_in[5];
    const float* Wq = (const float*)d_in[6];
    const float* bq = (const float*)d_in[7];
    const float* Wk = (const float*)d_in[8];
    const float* bk = (const float*)d_in[9];
    const float* Wo = (const float*)d_in[10];

    float* out  = (float*)d_out;
    float* attn = out + (size_t)BB*SS*DD;

    const int PROJ_SMEM  = 2 * STG;   // 110592
    const int SCORE_SMEM = 73728;
    const int PV_SMEM    = 2 * STG;   // 110592

    cudaFuncSetAttribute(proj_mma,   cudaFuncAttributeMaxDynamicSharedMemorySize, PROJ_SMEM);
    cudaFuncSetAttribute(score_mma,  cudaFuncAttributeMaxDynamicSharedMemorySize, SCORE_SMEM);
    cudaFuncSetAttribute(pvnorm_mma, cudaFuncAttributeMaxDynamicSharedMemorySize, PV_SMEM);

    proj_mma<<<dim3(SS/128, BB, 2*HH + 1), 256, PROJ_SMEM>>>(q, k, v, Wq, bq, Wk, bk, Wv, bv);
    score_mma<<<dim3(256, HH, BB), 256, SCORE_SMEM>>>(attn);
    combine_k<<<BB*HH*SS/8, 256>>>();
    pvnorm_mma<<<dim3(SS/128, HH, BB), 256, PV_SMEM>>>(attn);
    mean_kernel<<<BB*SS*DHH/256, 256>>>();
    outproj_kernel<<<dim3(SS/64, DD/64, BB), 256>>>(Wo, out);
}